// round 15
// baseline (speedup 1.0000x reference)
#include <cuda_runtime.h>

// Problem dims (fixed by the dataset): N=100000 nodes, F_in=512, HID=16,
// NCLS=40, E=3200000 directed edges (+N implicit self loops).
#define NMAX 100000
#define EMAX 3200000
#define FIN  512
#define HID  16
#define NCLS 40
#define SCAN_B 1024                          // nodes per scan block
#define NSB ((NMAX + SCAN_B - 1) / SCAN_B)   // 98 scan blocks

// gemm1 tiling (round-12 proven config: cp.async double-buffer, 2 rows/thread)
#define G1T 128            // threads per block
#define G1R 256            // rows per block (2 per thread)
#define G1C 16             // K columns per stage
#define NCH (FIN / G1C)    // 32 chunks
#define XSS 20             // x-tile row stride in floats (80B: 16B-aligned,
                           // conflict-free for 8-lane LDS.128 phases)
#define XTILE (G1R * XSS)  // floats per stage (5120)
#define G1_SMEM ((FIN * HID + 2 * XTILE) * 4)   // 32KB W + 40KB x = 72KB

// -------- device scratch (~27 MB total; no allocations) -----------------
// Symbols referenced ONLY in device code (host-passing a __device__ symbol
// passes the host shadow address — the rounds-4/5 failure).
__device__ float4 g_h[NMAX * HID / 4];   // h' = (x@W1)*dinv (layer-1 input)
__device__ float4 g_z[NMAX * HID / 4];   // z' = relu(agg1+b1)*dinv (layer-2 input)
__device__ float  g_dinv[NMAX];          // rsqrt(degree)
__device__ int    g_cnt[NMAX];           // in-degree / fill cursor (zeroed by
                                         // BSS init on run 1, by k_agg2 after)
__device__ int    g_off[NMAX + 1];       // CSR row offsets
__device__ int    g_adj[EMAX];           // CSR adjacency (src ids), 12.8 MB
__device__ int    g_bsum[NSB];           // scan partials
__device__ int    g_fmt64;               // 1 if edge_index is int64 on device

// ---------------------------------------------------------
// Detect edge_index element width (1 warp; g_cnt zeroing now lives in agg2).
__global__ void k_detect(const unsigned int* __restrict__ w) {
    if (threadIdx.x == 0) {
        unsigned int acc = 0;
#pragma unroll
        for (int k = 0; k < 128; k++) acc |= w[2 * k + 1];
        g_fmt64 = (acc == 0u) ? 1 : 0;
    }
}

// Histogram pass: 2 edges per thread, vectorized dst loads, dst half only.
__global__ void k_count(const int* __restrict__ w, int E, int n) {
    int e = (blockIdx.x * blockDim.x + threadIdx.x) * 2;
    if (e >= E) return;
    int d0, d1;
    if (g_fmt64) {
        int4 v = *reinterpret_cast<const int4*>(w + 2 * ((size_t)E + e));
        d0 = v.x; d1 = v.z;                // low words of 2 int64
    } else {
        int2 v = *reinterpret_cast<const int2*>(w + (size_t)E + e);
        d0 = v.x; d1 = v.y;
    }
    if ((unsigned)d0 >= (unsigned)n) d0 = 0;
    if ((unsigned)d1 >= (unsigned)n) d1 = 0;
    atomicAdd(&g_cnt[d0], 1);
    atomicAdd(&g_cnt[d1], 1);              // E is even: e+1 always valid
}

// Per-block exclusive scan of g_cnt -> g_off; block totals -> g_bsum.
// Also computes dinv = rsqrt(deg+1) and zeroes g_cnt (fill cursor).
__global__ void k_scan1(int n) {
    __shared__ int sh[SCAN_B];
    int i = blockIdx.x * SCAN_B + threadIdx.x;
    int v = (i < n) ? g_cnt[i] : 0;
    if (i < n) {
        g_dinv[i] = rsqrtf((float)v + 1.0f);
        g_cnt[i] = 0;
    }
    sh[threadIdx.x] = v;
    __syncthreads();
    for (int off = 1; off < SCAN_B; off <<= 1) {
        int t = (threadIdx.x >= off) ? sh[threadIdx.x - off] : 0;
        __syncthreads();
        sh[threadIdx.x] += t;
        __syncthreads();
    }
    if (i < n) g_off[i] = sh[threadIdx.x] - v;   // exclusive within block
    if (threadIdx.x == SCAN_B - 1) g_bsum[blockIdx.x] = sh[SCAN_B - 1];
}

// Folded scan2+scan3: every block redundantly exclusive-scans the 98 block
// sums in smem (cheap), then adds the block offset to its nodes.
__global__ void k_scan3(int E, int n) {
    __shared__ int pre[NSB];
    int t = threadIdx.x;
    int orig = 0;
    if (t < NSB) { orig = g_bsum[t]; pre[t] = orig; }
    __syncthreads();
    for (int off = 1; off < NSB; off <<= 1) {
        int v = (t >= off && t < NSB) ? pre[t - off] : 0;
        __syncthreads();
        if (t < NSB) pre[t] += v;
        __syncthreads();
    }
    if (t < NSB) pre[t] -= orig;          // exclusive
    __syncthreads();
    int i = blockIdx.x * blockDim.x + t;
    if (i < n) g_off[i] += pre[i / SCAN_B];
    if (i == 0) g_off[NMAX] = E;
}

// CSR fill: 2 edges per thread, vectorized src+dst loads.
__global__ void k_fill(const int* __restrict__ w, int E, int n) {
    int e = (blockIdx.x * blockDim.x + threadIdx.x) * 2;
    if (e >= E) return;
    int s0, s1, d0, d1;
    if (g_fmt64) {
        int4 sv = *reinterpret_cast<const int4*>(w + 2 * (size_t)e);
        int4 dv = *reinterpret_cast<const int4*>(w + 2 * ((size_t)E + e));
        s0 = sv.x; s1 = sv.z; d0 = dv.x; d1 = dv.z;
    } else {
        int2 sv = *reinterpret_cast<const int2*>(w + (size_t)e);
        int2 dv = *reinterpret_cast<const int2*>(w + (size_t)E + e);
        s0 = sv.x; s1 = sv.y; d0 = dv.x; d1 = dv.y;
    }
    if ((unsigned)s0 >= (unsigned)n) s0 = 0;
    if ((unsigned)s1 >= (unsigned)n) s1 = 0;
    if ((unsigned)d0 >= (unsigned)n) d0 = 0;
    if ((unsigned)d1 >= (unsigned)n) d1 = 0;
    int p0 = atomicAdd(&g_cnt[d0], 1);
    g_adj[g_off[d0] + p0] = s0;
    int p1 = atomicAdd(&g_cnt[d1], 1);
    g_adj[g_off[d1] + p1] = s1;
}

// ---------------------------------------------------------
// GEMM1: h' = (x @ W1) * dinv.  Round-12 proven structure + launch_bounds
// register headroom: the kernel is latency-bound at 2.4 warps/SMSP (grid
// 391 caps occupancy), so let ptxas use up to 256 regs to hoist LDS/x
// loads across k-iterations (default heuristic chose 85).
__global__ void __launch_bounds__(G1T, 2) k_gemm1(const float* __restrict__ x,
                                                  const float* __restrict__ W1, int n) {
    extern __shared__ float sm[];
    float* Ws = sm;                      // FIN*HID floats (32 KB)
    float* xs = sm + FIN * HID;          // 2 stages of XTILE floats

    int t = threadIdx.x;
    {   // W1 -> smem (2048 float4, 16 per thread); first sync covers this
        const float4* w4 = reinterpret_cast<const float4*>(W1);
        float4* ws4 = reinterpret_cast<float4*>(Ws);
#pragma unroll
        for (int i = 0; i < (FIN * HID / 4) / G1T; i++)
            ws4[t + G1T * i] = __ldg(&w4[t + G1T * i]);
    }

    int rowbase = blockIdx.x * G1R;

    unsigned long long xg;               // global-space base of x
    asm("cvta.to.global.u64 %0, %1;" : "=l"(xg) : "l"(x));
    unsigned int xs_u32;                 // shared-space base of xs
    asm("{ .reg .u64 tt; cvta.to.shared.u64 tt, %1; cvt.u32.u64 %0, tt; }"
        : "=r"(xs_u32) : "l"(xs));

    // two rows per thread: r0 = t, r1 = t + G1T (block-strided)
    unsigned long long acc0[HID / 2], acc1[HID / 2];
#pragma unroll
    for (int j = 0; j < HID / 2; j++) { acc0[j] = 0ull; acc1[j] = 0ull; }

    // Issue one chunk's loads into stage s (8 cp.async x 16B per thread).
    auto issue = [&](int c, int s) {
#pragma unroll
        for (int i = 0; i < 8; i++) {
            int f4 = t + G1T * i;
            int row = f4 >> 2;                 // 4 float4 per row-chunk
            int c4 = f4 & 3;
            int gr = rowbase + row;
            int ok = (gr < n) ? 16 : 0;
            int grc = (gr < n) ? gr : (n - 1);
            unsigned long long gaddr =
                xg + ((unsigned long long)grc * (FIN / 4) + (unsigned)(c * 4 + c4)) * 16ull;
            unsigned int saddr =
                xs_u32 + (unsigned)(s * XTILE + row * XSS + c4 * 4) * 4u;
            asm volatile("cp.async.cg.shared.global [%0], [%1], 16, %2;"
                         :: "r"(saddr), "l"(gaddr), "r"(ok));
        }
        asm volatile("cp.async.commit_group;" ::: "memory");
    };

    issue(0, 0);                         // prologue: 2 stages in flight
    issue(1, 1);

    for (int c = 0; c < NCH; c++) {
        asm volatile("cp.async.wait_group 1;" ::: "memory");   // stage c%2 ready
        __syncthreads();

        const float* xc = xs + (c & 1) * XTILE;
        const ulonglong2* wbase =
            reinterpret_cast<const ulonglong2*>(&Ws[c * G1C * HID]);
#pragma unroll
        for (int kk4 = 0; kk4 < G1C / 4; kk4++) {
            float4 xa = *reinterpret_cast<const float4*>(&xc[t * XSS + kk4 * 4]);
            float4 xb = *reinterpret_cast<const float4*>(&xc[(t + G1T) * XSS + kk4 * 4]);
            float va[4] = {xa.x, xa.y, xa.z, xa.w};
            float vb[4] = {xb.x, xb.y, xb.z, xb.w};
#pragma unroll
            for (int u = 0; u < 4; u++) {
                int k = kk4 * 4 + u;
                unsigned long long xv0, xv1;
                asm("mov.b64 %0, {%1, %1};" : "=l"(xv0) : "f"(va[u]));
                asm("mov.b64 %0, {%1, %1};" : "=l"(xv1) : "f"(vb[u]));
                const ulonglong2* w2 = wbase + k * (HID / 4);  // 4 ull2 per k
#pragma unroll
                for (int p = 0; p < HID / 4; p++) {
                    ulonglong2 wp = w2[p];                     // LDS.128 -> 2 u64
                    asm("fma.rn.f32x2 %0, %1, %2, %0;"
                        : "+l"(acc0[2 * p]) : "l"(xv0), "l"(wp.x));
                    asm("fma.rn.f32x2 %0, %1, %2, %0;"
                        : "+l"(acc0[2 * p + 1]) : "l"(xv0), "l"(wp.y));
                    asm("fma.rn.f32x2 %0, %1, %2, %0;"
                        : "+l"(acc1[2 * p]) : "l"(xv1), "l"(wp.x));
                    asm("fma.rn.f32x2 %0, %1, %2, %0;"
                        : "+l"(acc1[2 * p + 1]) : "l"(xv1), "l"(wp.y));
                }
            }
        }
        __syncthreads();                 // stage c%2 fully consumed

        if (c + 2 < NCH) issue(c + 2, c & 1);
        else asm volatile("cp.async.commit_group;" ::: "memory");  // keep counts
    }

    int r0 = rowbase + t;
    if (r0 < n) {
        float s = g_dinv[r0];
        float4* h = g_h + (size_t)r0 * (HID / 4);
#pragma unroll
        for (int q = 0; q < HID / 4; q++) {
            float a, b2, c2, d;
            asm("mov.b64 {%0, %1}, %2;" : "=f"(a), "=f"(b2) : "l"(acc0[2 * q]));
            asm("mov.b64 {%0, %1}, %2;" : "=f"(c2), "=f"(d) : "l"(acc0[2 * q + 1]));
            h[q] = make_float4(a * s, b2 * s, c2 * s, d * s);
        }
    }
    int r1 = rowbase + t + G1T;
    if (r1 < n) {
        float s = g_dinv[r1];
        float4* h = g_h + (size_t)r1 * (HID / 4);
#pragma unroll
        for (int q = 0; q < HID / 4; q++) {
            float a, b2, c2, d;
            asm("mov.b64 {%0, %1}, %2;" : "=f"(a), "=f"(b2) : "l"(acc1[2 * q]));
            asm("mov.b64 {%0, %1}, %2;" : "=f"(c2), "=f"(d) : "l"(acc1[2 * q + 1]));
            h[q] = make_float4(a * s, b2 * s, c2 * s, d * s);
        }
    }
}

// ---------------------------------------------------------
// Layer-1 aggregation, one WARP per dst node, zero atomics, CSR list.
// Self-feature/dinv loads hoisted above the gather loop (latency hides).
//   z'[d] = relu( dinv[d] * (sum_e h'[src] + h'[d]) + b1 ) * dinv[d]
__global__ void k_agg1(const float* __restrict__ b1, int n) {
    int gw = (blockIdx.x * blockDim.x + threadIdx.x) >> 5;
    if (gw >= n) return;
    int lane = threadIdx.x & 31;
    int grp = lane >> 2;
    int q = lane & 3;

    int beg = g_off[gw];
    int end = g_off[gw + 1];
    float dd = g_dinv[gw];
    float4 selfv = make_float4(0.f, 0.f, 0.f, 0.f);
    float4 b = make_float4(0.f, 0.f, 0.f, 0.f);
    if (lane < 4) {
        selfv = g_h[(size_t)gw * (HID / 4) + lane];
        b = reinterpret_cast<const float4*>(b1)[lane];
    }

    float4 acc = make_float4(0.f, 0.f, 0.f, 0.f);
    int i = beg + grp;
    for (; i + 24 < end; i += 32) {
        int s0 = __ldg(g_adj + i);
        int s1 = __ldg(g_adj + i + 8);
        int s2 = __ldg(g_adj + i + 16);
        int s3 = __ldg(g_adj + i + 24);
        float4 v0 = __ldg(g_h + (size_t)s0 * (HID / 4) + q);
        float4 v1 = __ldg(g_h + (size_t)s1 * (HID / 4) + q);
        float4 v2 = __ldg(g_h + (size_t)s2 * (HID / 4) + q);
        float4 v3 = __ldg(g_h + (size_t)s3 * (HID / 4) + q);
        acc.x += (v0.x + v1.x) + (v2.x + v3.x);
        acc.y += (v0.y + v1.y) + (v2.y + v3.y);
        acc.z += (v0.z + v1.z) + (v2.z + v3.z);
        acc.w += (v0.w + v1.w) + (v2.w + v3.w);
    }
    for (; i < end; i += 8) {
        int s = __ldg(g_adj + i);
        float4 v = __ldg(g_h + (size_t)s * (HID / 4) + q);
        acc.x += v.x; acc.y += v.y; acc.z += v.z; acc.w += v.w;
    }
#pragma unroll
    for (int off = 16; off >= 4; off >>= 1) {
        acc.x += __shfl_down_sync(0xffffffffu, acc.x, off);
        acc.y += __shfl_down_sync(0xffffffffu, acc.y, off);
        acc.z += __shfl_down_sync(0xffffffffu, acc.z, off);
        acc.w += __shfl_down_sync(0xffffffffu, acc.w, off);
    }
    if (lane < 4) {
        acc.x += selfv.x; acc.y += selfv.y; acc.z += selfv.z; acc.w += selfv.w;
        float4 r;
        r.x = fmaxf(fmaf(dd, acc.x, b.x), 0.f) * dd;
        r.y = fmaxf(fmaf(dd, acc.y, b.y), 0.f) * dd;
        r.z = fmaxf(fmaf(dd, acc.z, b.z), 0.f) * dd;
        r.w = fmaxf(fmaf(dd, acc.w, b.w), 0.f) * dd;
        g_z[(size_t)gw * (HID / 4) + lane] = r;
    }
}

// ---------------------------------------------------------
// Layer-2 aggregation fused with the 16->40 output GEMM + b2.
// Tail also re-zeroes g_cnt for the next replay (cnt is dead after k_fill;
// BSS zero-init covers the very first execution).
__global__ void k_agg2(const float* __restrict__ W2,
                       const float* __restrict__ b2,
                       float* __restrict__ out, int n) {
    __shared__ float W2s[HID * NCLS];
    __shared__ float b2s[NCLS];
    for (int i = threadIdx.x; i < HID * NCLS; i += blockDim.x) W2s[i] = W2[i];
    for (int i = threadIdx.x; i < NCLS; i += blockDim.x) b2s[i] = b2[i];
    __syncthreads();

    int gw = (blockIdx.x * blockDim.x + threadIdx.x) >> 5;
    if (gw >= n) return;
    int lane = threadIdx.x & 31;
    int grp = lane >> 2;
    int q = lane & 3;

    int beg = g_off[gw];
    int end = g_off[gw + 1];
    float dd = g_dinv[gw];
    float4 selfv = make_float4(0.f, 0.f, 0.f, 0.f);
    if (lane < 4) selfv = g_z[(size_t)gw * (HID / 4) + lane];
    if (lane == 0) g_cnt[gw] = 0;          // reset cursor for next replay

    float4 acc = make_float4(0.f, 0.f, 0.f, 0.f);
    int i = beg + grp;
    for (; i + 24 < end; i += 32) {
        int s0 = __ldg(g_adj + i);
        int s1 = __ldg(g_adj + i + 8);
        int s2 = __ldg(g_adj + i + 16);
        int s3 = __ldg(g_adj + i + 24);
        float4 v0 = __ldg(g_z + (size_t)s0 * (HID / 4) + q);
        float4 v1 = __ldg(g_z + (size_t)s1 * (HID / 4) + q);
        float4 v2 = __ldg(g_z + (size_t)s2 * (HID / 4) + q);
        float4 v3 = __ldg(g_z + (size_t)s3 * (HID / 4) + q);
        acc.x += (v0.x + v1.x) + (v2.x + v3.x);
        acc.y += (v0.y + v1.y) + (v2.y + v3.y);
        acc.z += (v0.z + v1.z) + (v2.z + v3.z);
        acc.w += (v0.w + v1.w) + (v2.w + v3.w);
    }
    for (; i < end; i += 8) {
        int s = __ldg(g_adj + i);
        float4 v = __ldg(g_z + (size_t)s * (HID / 4) + q);
        acc.x += v.x; acc.y += v.y; acc.z += v.z; acc.w += v.w;
    }
#pragma unroll
    for (int off = 16; off >= 4; off >>= 1) {
        acc.x += __shfl_down_sync(0xffffffffu, acc.x, off);
        acc.y += __shfl_down_sync(0xffffffffu, acc.y, off);
        acc.z += __shfl_down_sync(0xffffffffu, acc.z, off);
        acc.w += __shfl_down_sync(0xffffffffu, acc.w, off);
    }
    if (lane < 4) {                                        // add self (z')
        acc.x += selfv.x; acc.y += selfv.y; acc.z += selfv.z; acc.w += selfv.w;
    }
    float a[HID];
#pragma unroll
    for (int Q = 0; Q < 4; Q++) {
        a[Q*4+0] = __shfl_sync(0xffffffffu, acc.x, Q);
        a[Q*4+1] = __shfl_sync(0xffffffffu, acc.y, Q);
        a[Q*4+2] = __shfl_sync(0xffffffffu, acc.z, Q);
        a[Q*4+3] = __shfl_sync(0xffffffffu, acc.w, Q);
    }

    float s1 = 0.f;
#pragma unroll
    for (int k = 0; k < HID; k++) s1 = fmaf(a[k], W2s[k * NCLS + lane], s1);
    out[(size_t)gw * NCLS + lane] = fmaf(dd, s1, b2s[lane]);

    if (lane < NCLS - 32) {
        float s2 = 0.f;
#pragma unroll
        for (int k = 0; k < HID; k++) s2 = fmaf(a[k], W2s[k * NCLS + 32 + lane], s2);
        out[(size_t)gw * NCLS + 32 + lane] = fmaf(dd, s2, b2s[32 + lane]);
    }
}

// ---------------------------------------------------------
extern "C" void kernel_launch(void* const* d_in, const int* in_sizes, int n_in,
                              void* d_out, int out_size) {
    // Identify inputs by unique element counts (ordering-robust).
    const float* x  = nullptr;
    const int*   ei = nullptr;
    const float* W1 = nullptr;
    const float* b1 = nullptr;
    const float* W2 = nullptr;
    const float* b2 = nullptr;
    for (int i = 0; i < n_in; i++) {
        switch (in_sizes[i]) {
            case 51200000: x  = (const float*)d_in[i]; break;
            case 6400000:  ei = (const int*)d_in[i];   break;
            case 8192:     W1 = (const float*)d_in[i]; break;
            case 16:       b1 = (const float*)d_in[i]; break;
            case 640:      W2 = (const float*)d_in[i]; break;
            case 40:       b2 = (const float*)d_in[i]; break;
            default: break;
        }
    }
    float* out = (float*)d_out;
    const int n = NMAX;
    const int E = EMAX;
    (void)out_size;

    static int inited = 0;
    if (!inited) {
        cudaFuncSetAttribute(k_gemm1, cudaFuncAttributeMaxDynamicSharedMemorySize,
                             G1_SMEM);
        inited = 1;
    }

    int eblocks = (E / 2 + 255) / 256;                    // 2 edges / thread
    k_detect<<<1, 32>>>((const unsigned int*)ei);
    k_count<<<eblocks, 256>>>(ei, E, n);
    k_scan1<<<NSB, SCAN_B>>>(n);                          // dinv ready
    k_gemm1<<<(n + G1R - 1) / G1R, G1T, G1_SMEM>>>(x, W1, n);   // index 3 (ncu)
    k_scan3<<<(n + 255) / 256, 256>>>(E, n);
    k_fill<<<eblocks, 256>>>(ei, E, n);

    int agg_blocks = (n * 32 + 255) / 256;                // 1 warp / node
    k_agg1<<<agg_blocks, 256>>>(b1, n);
    k_agg2<<<agg_blocks, 256>>>(W2, b2, out, n);
}

// round 16
// speedup vs baseline: 1.0182x; 1.0182x over previous
#include <cuda_runtime.h>

// Problem dims (fixed by the dataset): N=100000 nodes, F_in=512, HID=16,
// NCLS=40, E=3200000 directed edges (+N implicit self loops).
#define NMAX 100000
#define EMAX 3200000
#define FIN  512
#define HID  16
#define NCLS 40
#define SCAN_B 1024                          // nodes per scan block
#define NSB ((NMAX + SCAN_B - 1) / SCAN_B)   // 98 scan blocks

// gemm1 tiling (round-12 proven config: cp.async double-buffer, 2 rows/thread)
#define G1T 128            // threads per block
#define G1R 256            // rows per block (2 per thread)
#define G1C 16             // K columns per stage
#define NCH (FIN / G1C)    // 32 chunks
#define XSS 20             // x-tile row stride in floats (80B: 16B-aligned,
                           // conflict-free for 8-lane LDS.128 phases)
#define XTILE (G1R * XSS)  // floats per stage (5120)
#define G1_SMEM ((FIN * HID + 2 * XTILE) * 4)   // 32KB W + 40KB x = 72KB

// -------- device scratch (~27 MB total; no allocations) -----------------
// Symbols referenced ONLY in device code (host-passing a __device__ symbol
// passes the host shadow address — the rounds-4/5 failure).
__device__ float4 g_h[NMAX * HID / 4];   // h' = (x@W1)*dinv (layer-1 input)
__device__ float4 g_z[NMAX * HID / 4];   // z' = relu(agg1+b1)*dinv (layer-2 input)
__device__ float  g_dinv[NMAX];          // rsqrt(degree)
__device__ int    g_cnt[NMAX];           // in-degree / fill cursor
__device__ int    g_off[NMAX + 1];       // CSR row offsets
__device__ int    g_adj[EMAX];           // CSR adjacency (src ids), 12.8 MB
__device__ int    g_bsum[NSB];           // scan partials
__device__ int    g_fmt64;               // 1 if edge_index is int64 on device

// ---------------------------------------------------------
// Merged: zero counters + detect edge_index element width.
__global__ void k_init(const unsigned int* __restrict__ w, int n) {
    int i = blockIdx.x * blockDim.x + threadIdx.x;
    if (i < n) g_cnt[i] = 0;
    if (i == 0) {
        unsigned int acc = 0;
#pragma unroll
        for (int k = 0; k < 128; k++) acc |= w[2 * k + 1];
        g_fmt64 = (acc == 0u) ? 1 : 0;
    }
}

__device__ __forceinline__ void load_edge(const int* __restrict__ w, int e,
                                          int E, int n, int& s, int& d) {
    if (g_fmt64) {
        s = w[2 * (size_t)e];
        d = w[2 * ((size_t)E + e)];
    } else {
        s = w[e];
        d = w[(size_t)E + e];
    }
    if ((unsigned)s >= (unsigned)n) s = 0;
    if ((unsigned)d >= (unsigned)n) d = 0;
}

// Histogram pass touches ONLY the dst half of edge_index.
__global__ void k_count(const int* __restrict__ w, int E, int n) {
    int e = blockIdx.x * blockDim.x + threadIdx.x;
    if (e >= E) return;
    int d = g_fmt64 ? w[2 * ((size_t)E + e)] : w[(size_t)E + e];
    if ((unsigned)d >= (unsigned)n) d = 0;
    atomicAdd(&g_cnt[d], 1);
}

// Per-block exclusive scan of g_cnt -> g_off; block totals -> g_bsum.
// Also computes dinv = rsqrt(deg+1) and zeroes g_cnt (fill cursor).
__global__ void k_scan1(int n) {
    __shared__ int sh[SCAN_B];
    int i = blockIdx.x * SCAN_B + threadIdx.x;
    int v = (i < n) ? g_cnt[i] : 0;
    if (i < n) {
        g_dinv[i] = rsqrtf((float)v + 1.0f);
        g_cnt[i] = 0;
    }
    sh[threadIdx.x] = v;
    __syncthreads();
    for (int off = 1; off < SCAN_B; off <<= 1) {
        int t = (threadIdx.x >= off) ? sh[threadIdx.x - off] : 0;
        __syncthreads();
        sh[threadIdx.x] += t;
        __syncthreads();
    }
    if (i < n) g_off[i] = sh[threadIdx.x] - v;   // exclusive within block
    if (threadIdx.x == SCAN_B - 1) g_bsum[blockIdx.x] = sh[SCAN_B - 1];
}

// Folded scan2+scan3: every block redundantly exclusive-scans the 98 block
// sums in smem (cheap), then adds the block offset to its nodes.
__global__ void k_scan3(int E, int n) {
    __shared__ int pre[NSB];
    int t = threadIdx.x;
    int orig = 0;
    if (t < NSB) { orig = g_bsum[t]; pre[t] = orig; }
    __syncthreads();
    for (int off = 1; off < NSB; off <<= 1) {
        int v = (t >= off && t < NSB) ? pre[t - off] : 0;
        __syncthreads();
        if (t < NSB) pre[t] += v;
        __syncthreads();
    }
    if (t < NSB) pre[t] -= orig;          // exclusive
    __syncthreads();
    int i = blockIdx.x * blockDim.x + t;
    if (i < n) g_off[i] += pre[i / SCAN_B];
    if (i == 0) g_off[NMAX] = E;
}

__global__ void k_fill(const int* __restrict__ w, int E, int n) {
    int e = blockIdx.x * blockDim.x + threadIdx.x;
    if (e >= E) return;
    int s, d;
    load_edge(w, e, E, n, s, d);
    int pos = atomicAdd(&g_cnt[d], 1);
    g_adj[g_off[d] + pos] = s;
}

// ---------------------------------------------------------
// GEMM1: h' = (x @ W1) * dinv.  Round-12 structure + launch_bounds register
// headroom (measured win: 68.5 -> 65.0us; regs 85 -> 120, deeper ILP window
// for the latency-bound 2.4-warps/SMSP regime).
__global__ void __launch_bounds__(G1T, 2) k_gemm1(const float* __restrict__ x,
                                                  const float* __restrict__ W1, int n) {
    extern __shared__ float sm[];
    float* Ws = sm;                      // FIN*HID floats (32 KB)
    float* xs = sm + FIN * HID;          // 2 stages of XTILE floats

    int t = threadIdx.x;
    {   // W1 -> smem (2048 float4, 16 per thread); first sync covers this
        const float4* w4 = reinterpret_cast<const float4*>(W1);
        float4* ws4 = reinterpret_cast<float4*>(Ws);
#pragma unroll
        for (int i = 0; i < (FIN * HID / 4) / G1T; i++)
            ws4[t + G1T * i] = __ldg(&w4[t + G1T * i]);
    }

    int rowbase = blockIdx.x * G1R;

    unsigned long long xg;               // global-space base of x
    asm("cvta.to.global.u64 %0, %1;" : "=l"(xg) : "l"(x));
    unsigned int xs_u32;                 // shared-space base of xs
    asm("{ .reg .u64 tt; cvta.to.shared.u64 tt, %1; cvt.u32.u64 %0, tt; }"
        : "=r"(xs_u32) : "l"(xs));

    // two rows per thread: r0 = t, r1 = t + G1T (block-strided)
    unsigned long long acc0[HID / 2], acc1[HID / 2];
#pragma unroll
    for (int j = 0; j < HID / 2; j++) { acc0[j] = 0ull; acc1[j] = 0ull; }

    // Issue one chunk's loads into stage s (8 cp.async x 16B per thread).
    auto issue = [&](int c, int s) {
#pragma unroll
        for (int i = 0; i < 8; i++) {
            int f4 = t + G1T * i;
            int row = f4 >> 2;                 // 4 float4 per row-chunk
            int c4 = f4 & 3;
            int gr = rowbase + row;
            int ok = (gr < n) ? 16 : 0;
            int grc = (gr < n) ? gr : (n - 1);
            unsigned long long gaddr =
                xg + ((unsigned long long)grc * (FIN / 4) + (unsigned)(c * 4 + c4)) * 16ull;
            unsigned int saddr =
                xs_u32 + (unsigned)(s * XTILE + row * XSS + c4 * 4) * 4u;
            asm volatile("cp.async.cg.shared.global [%0], [%1], 16, %2;"
                         :: "r"(saddr), "l"(gaddr), "r"(ok));
        }
        asm volatile("cp.async.commit_group;" ::: "memory");
    };

    issue(0, 0);                         // prologue: 2 stages in flight
    issue(1, 1);

    for (int c = 0; c < NCH; c++) {
        asm volatile("cp.async.wait_group 1;" ::: "memory");   // stage c%2 ready
        __syncthreads();

        const float* xc = xs + (c & 1) * XTILE;
        const ulonglong2* wbase =
            reinterpret_cast<const ulonglong2*>(&Ws[c * G1C * HID]);
#pragma unroll
        for (int kk4 = 0; kk4 < G1C / 4; kk4++) {
            float4 xa = *reinterpret_cast<const float4*>(&xc[t * XSS + kk4 * 4]);
            float4 xb = *reinterpret_cast<const float4*>(&xc[(t + G1T) * XSS + kk4 * 4]);
            float va[4] = {xa.x, xa.y, xa.z, xa.w};
            float vb[4] = {xb.x, xb.y, xb.z, xb.w};
#pragma unroll
            for (int u = 0; u < 4; u++) {
                int k = kk4 * 4 + u;
                unsigned long long xv0, xv1;
                asm("mov.b64 %0, {%1, %1};" : "=l"(xv0) : "f"(va[u]));
                asm("mov.b64 %0, {%1, %1};" : "=l"(xv1) : "f"(vb[u]));
                const ulonglong2* w2 = wbase + k * (HID / 4);  // 4 ull2 per k
#pragma unroll
                for (int p = 0; p < HID / 4; p++) {
                    ulonglong2 wp = w2[p];                     // LDS.128 -> 2 u64
                    asm("fma.rn.f32x2 %0, %1, %2, %0;"
                        : "+l"(acc0[2 * p]) : "l"(xv0), "l"(wp.x));
                    asm("fma.rn.f32x2 %0, %1, %2, %0;"
                        : "+l"(acc0[2 * p + 1]) : "l"(xv0), "l"(wp.y));
                    asm("fma.rn.f32x2 %0, %1, %2, %0;"
                        : "+l"(acc1[2 * p]) : "l"(xv1), "l"(wp.x));
                    asm("fma.rn.f32x2 %0, %1, %2, %0;"
                        : "+l"(acc1[2 * p + 1]) : "l"(xv1), "l"(wp.y));
                }
            }
        }
        __syncthreads();                 // stage c%2 fully consumed

        if (c + 2 < NCH) issue(c + 2, c & 1);
        else asm volatile("cp.async.commit_group;" ::: "memory");  // keep counts
    }

    int r0 = rowbase + t;
    if (r0 < n) {
        float s = g_dinv[r0];
        float4* h = g_h + (size_t)r0 * (HID / 4);
#pragma unroll
        for (int q = 0; q < HID / 4; q++) {
            float a, b2, c2, d;
            asm("mov.b64 {%0, %1}, %2;" : "=f"(a), "=f"(b2) : "l"(acc0[2 * q]));
            asm("mov.b64 {%0, %1}, %2;" : "=f"(c2), "=f"(d) : "l"(acc0[2 * q + 1]));
            h[q] = make_float4(a * s, b2 * s, c2 * s, d * s);
        }
    }
    int r1 = rowbase + t + G1T;
    if (r1 < n) {
        float s = g_dinv[r1];
        float4* h = g_h + (size_t)r1 * (HID / 4);
#pragma unroll
        for (int q = 0; q < HID / 4; q++) {
            float a, b2, c2, d;
            asm("mov.b64 {%0, %1}, %2;" : "=f"(a), "=f"(b2) : "l"(acc1[2 * q]));
            asm("mov.b64 {%0, %1}, %2;" : "=f"(c2), "=f"(d) : "l"(acc1[2 * q + 1]));
            h[q] = make_float4(a * s, b2 * s, c2 * s, d * s);
        }
    }
}

// ---------------------------------------------------------
// Layer-1 aggregation, one WARP per dst node, zero atomics, CSR list.
// Gather unrolled x4 (avg degree 32 -> one iteration; MLP 4/lane).
//   z'[d] = relu( dinv[d] * (sum_e h'[src] + h'[d]) + b1 ) * dinv[d]
__global__ void k_agg1(const float* __restrict__ b1, int n) {
    int gw = (blockIdx.x * blockDim.x + threadIdx.x) >> 5;
    if (gw >= n) return;
    int lane = threadIdx.x & 31;
    int grp = lane >> 2;
    int q = lane & 3;

    int beg = g_off[gw];
    int end = g_off[gw + 1];

    float4 acc = make_float4(0.f, 0.f, 0.f, 0.f);
    int i = beg + grp;
    for (; i + 24 < end; i += 32) {
        int s0 = __ldg(g_adj + i);
        int s1 = __ldg(g_adj + i + 8);
        int s2 = __ldg(g_adj + i + 16);
        int s3 = __ldg(g_adj + i + 24);
        float4 v0 = __ldg(g_h + (size_t)s0 * (HID / 4) + q);
        float4 v1 = __ldg(g_h + (size_t)s1 * (HID / 4) + q);
        float4 v2 = __ldg(g_h + (size_t)s2 * (HID / 4) + q);
        float4 v3 = __ldg(g_h + (size_t)s3 * (HID / 4) + q);
        acc.x += (v0.x + v1.x) + (v2.x + v3.x);
        acc.y += (v0.y + v1.y) + (v2.y + v3.y);
        acc.z += (v0.z + v1.z) + (v2.z + v3.z);
        acc.w += (v0.w + v1.w) + (v2.w + v3.w);
    }
    for (; i < end; i += 8) {
        int s = __ldg(g_adj + i);
        float4 v = __ldg(g_h + (size_t)s * (HID / 4) + q);
        acc.x += v.x; acc.y += v.y; acc.z += v.z; acc.w += v.w;
    }
#pragma unroll
    for (int off = 16; off >= 4; off >>= 1) {
        acc.x += __shfl_down_sync(0xffffffffu, acc.x, off);
        acc.y += __shfl_down_sync(0xffffffffu, acc.y, off);
        acc.z += __shfl_down_sync(0xffffffffu, acc.z, off);
        acc.w += __shfl_down_sync(0xffffffffu, acc.w, off);
    }
    if (lane < 4) {
        float4 v = g_h[(size_t)gw * (HID / 4) + lane];     // self (h')
        acc.x += v.x; acc.y += v.y; acc.z += v.z; acc.w += v.w;
        float dd = g_dinv[gw];
        float4 b = reinterpret_cast<const float4*>(b1)[lane];
        float4 r;
        r.x = fmaxf(fmaf(dd, acc.x, b.x), 0.f) * dd;
        r.y = fmaxf(fmaf(dd, acc.y, b.y), 0.f) * dd;
        r.z = fmaxf(fmaf(dd, acc.z, b.z), 0.f) * dd;
        r.w = fmaxf(fmaf(dd, acc.w, b.w), 0.f) * dd;
        g_z[(size_t)gw * (HID / 4) + lane] = r;
    }
}

// ---------------------------------------------------------
// Layer-2 aggregation fused with the 16->40 output GEMM + b2.
__global__ void k_agg2(const float* __restrict__ W2,
                       const float* __restrict__ b2,
                       float* __restrict__ out, int n) {
    __shared__ float W2s[HID * NCLS];
    __shared__ float b2s[NCLS];
    for (int i = threadIdx.x; i < HID * NCLS; i += blockDim.x) W2s[i] = W2[i];
    for (int i = threadIdx.x; i < NCLS; i += blockDim.x) b2s[i] = b2[i];
    __syncthreads();

    int gw = (blockIdx.x * blockDim.x + threadIdx.x) >> 5;
    if (gw >= n) return;
    int lane = threadIdx.x & 31;
    int grp = lane >> 2;
    int q = lane & 3;

    int beg = g_off[gw];
    int end = g_off[gw + 1];

    float4 acc = make_float4(0.f, 0.f, 0.f, 0.f);
    int i = beg + grp;
    for (; i + 24 < end; i += 32) {
        int s0 = __ldg(g_adj + i);
        int s1 = __ldg(g_adj + i + 8);
        int s2 = __ldg(g_adj + i + 16);
        int s3 = __ldg(g_adj + i + 24);
        float4 v0 = __ldg(g_z + (size_t)s0 * (HID / 4) + q);
        float4 v1 = __ldg(g_z + (size_t)s1 * (HID / 4) + q);
        float4 v2 = __ldg(g_z + (size_t)s2 * (HID / 4) + q);
        float4 v3 = __ldg(g_z + (size_t)s3 * (HID / 4) + q);
        acc.x += (v0.x + v1.x) + (v2.x + v3.x);
        acc.y += (v0.y + v1.y) + (v2.y + v3.y);
        acc.z += (v0.z + v1.z) + (v2.z + v3.z);
        acc.w += (v0.w + v1.w) + (v2.w + v3.w);
    }
    for (; i < end; i += 8) {
        int s = __ldg(g_adj + i);
        float4 v = __ldg(g_z + (size_t)s * (HID / 4) + q);
        acc.x += v.x; acc.y += v.y; acc.z += v.z; acc.w += v.w;
    }
#pragma unroll
    for (int off = 16; off >= 4; off >>= 1) {
        acc.x += __shfl_down_sync(0xffffffffu, acc.x, off);
        acc.y += __shfl_down_sync(0xffffffffu, acc.y, off);
        acc.z += __shfl_down_sync(0xffffffffu, acc.z, off);
        acc.w += __shfl_down_sync(0xffffffffu, acc.w, off);
    }
    if (lane < 4) {                                        // add self (z')
        float4 v = g_z[(size_t)gw * (HID / 4) + lane];
        acc.x += v.x; acc.y += v.y; acc.z += v.z; acc.w += v.w;
    }
    float a[HID];
#pragma unroll
    for (int Q = 0; Q < 4; Q++) {
        a[Q*4+0] = __shfl_sync(0xffffffffu, acc.x, Q);
        a[Q*4+1] = __shfl_sync(0xffffffffu, acc.y, Q);
        a[Q*4+2] = __shfl_sync(0xffffffffu, acc.z, Q);
        a[Q*4+3] = __shfl_sync(0xffffffffu, acc.w, Q);
    }
    float dd = g_dinv[gw];

    float s1 = 0.f;
#pragma unroll
    for (int k = 0; k < HID; k++) s1 = fmaf(a[k], W2s[k * NCLS + lane], s1);
    out[(size_t)gw * NCLS + lane] = fmaf(dd, s1, b2s[lane]);

    if (lane < NCLS - 32) {
        float s2 = 0.f;
#pragma unroll
        for (int k = 0; k < HID; k++) s2 = fmaf(a[k], W2s[k * NCLS + 32 + lane], s2);
        out[(size_t)gw * NCLS + 32 + lane] = fmaf(dd, s2, b2s[32 + lane]);
    }
}

// ---------------------------------------------------------
extern "C" void kernel_launch(void* const* d_in, const int* in_sizes, int n_in,
                              void* d_out, int out_size) {
    // Identify inputs by unique element counts (ordering-robust).
    const float* x  = nullptr;
    const int*   ei = nullptr;
    const float* W1 = nullptr;
    const float* b1 = nullptr;
    const float* W2 = nullptr;
    const float* b2 = nullptr;
    for (int i = 0; i < n_in; i++) {
        switch (in_sizes[i]) {
            case 51200000: x  = (const float*)d_in[i]; break;
            case 6400000:  ei = (const int*)d_in[i];   break;
            case 8192:     W1 = (const float*)d_in[i]; break;
            case 16:       b1 = (const float*)d_in[i]; break;
            case 640:      W2 = (const float*)d_in[i]; break;
            case 40:       b2 = (const float*)d_in[i]; break;
            default: break;
        }
    }
    float* out = (float*)d_out;
    const int n = NMAX;
    const int E = EMAX;
    (void)out_size;

    static int inited = 0;
    if (!inited) {
        cudaFuncSetAttribute(k_gemm1, cudaFuncAttributeMaxDynamicSharedMemorySize,
                             G1_SMEM);
        inited = 1;
    }

    k_init<<<(n + 255) / 256, 256>>>((const unsigned int*)ei, n);
    k_count<<<(E + 255) / 256, 256>>>(ei, E, n);
    k_scan1<<<NSB, SCAN_B>>>(n);                          // dinv ready
    k_gemm1<<<(n + G1R - 1) / G1R, G1T, G1_SMEM>>>(x, W1, n);
    k_scan3<<<(n + 255) / 256, 256>>>(E, n);
    k_fill<<<(E + 255) / 256, 256>>>(ei, E, n);

    int agg_blocks = (n * 32 + 255) / 256;                // 1 warp / node
    k_agg1<<<agg_blocks, 256>>>(b1, n);
    k_agg2<<<agg_blocks, 256>>>(W2, b2, out, n);
}